// round 9
// baseline (speedup 1.0000x reference)
#include <cuda_runtime.h>

// MemN2N on GB300 (sm_103a)
// B=128, M=200, S=20, D=128, V=100000, NC=10000, CL=10, 3 hops.
// Inputs: stories(i64), queries(i64), candidates(i64),
//         A_tab(f32 V*D), W_tab(f32 V*D), H_w(f32 D*D)
// Output: logits f32 [B, NC]
//
// K1 k_gather: story gathers -> g_m, candidate gathers -> g_csT (transposed,
//              via smem transpose). 313 MB L2->SM, pinned at the ~6300 B/cyc
//              LTS cap (~28us).
// K2 k_hops:   per-b block, 3 hops in smem; writes g_uT transposed.
// K3 k_logits: GEMM out = U @ CS^T from transposed smem tiles, 8b x 8c thread
//              tile, c-pair FFMA2 accumulators. 4 LDS.128 per 32 FFMA2 ->
//              crossbar == FFMA2 pipe (balanced). grid 148 = 1 CTA/SM exactly.

#define NB   128
#define NM   200
#define NS   20
#define ND   128
#define NCN  10000
#define NCP  10048   // padded candidate count (1256 blocks * 8)
#define NCL  10

__device__ float g_m[NB * NM * ND];     // 13.1 MB memory encodings
__device__ float g_csT[ND * NCP];       // 5.1 MB candidate sums, TRANSPOSED [k][c]
__device__ float g_uT[ND * NB];         // query state after hops, TRANSPOSED [k][b]

__device__ __forceinline__ int detect64(const int* __restrict__ p) {
    // values < 100000: if int64 (LE), high words of first elements are 0.
    return (p[1] == 0 && p[3] == 0 && p[5] == 0 && p[7] == 0) ? 1 : 0;
}

// ---------------------------------------------------------------------------
// K1: all gathers. Blocks [0,3200): story warps -> g_m. Blocks [3200,4456):
// 8 candidates per block -> smem -> transposed write to g_csT.
__global__ __launch_bounds__(256) void k_gather(const int* __restrict__ stories,
                                                const int* __restrict__ cand,
                                                const float4* __restrict__ A4,
                                                const float4* __restrict__ W4) {
    __shared__ float s_cs[8][128];
    int tid  = threadIdx.x;
    int lane = tid & 31;
    int wid  = tid >> 5;

    if (blockIdx.x < 3200) {
        int w = blockIdx.x * 8 + wid;          // story row, < 25600
        int is64 = detect64(stories);
        int idx[NS];
        if (is64) {
            const int* p = stories + (size_t)w * NS * 2;
#pragma unroll
            for (int s = 0; s < NS; s++) idx[s] = p[2 * s];
        } else {
            const int* p = stories + (size_t)w * NS;
#pragma unroll
            for (int s = 0; s < NS; s++) idx[s] = p[s];
        }
        float4 acc = make_float4(0.f, 0.f, 0.f, 0.f);
#pragma unroll
        for (int c0 = 0; c0 < NS; c0 += 5) {
            float4 v[5];
#pragma unroll
            for (int j = 0; j < 5; j++)
                v[j] = A4[(size_t)idx[c0 + j] * 32 + lane];   // row 0 valid
#pragma unroll
            for (int j = 0; j < 5; j++)
                if (idx[c0 + j] != 0) {
                    acc.x += v[j].x; acc.y += v[j].y;
                    acc.z += v[j].z; acc.w += v[j].w;
                }
        }
        reinterpret_cast<float4*>(g_m)[(size_t)w * 32 + lane] = acc;
    } else {
        int cb = blockIdx.x - 3200;            // 0..1255
        int c  = cb * 8 + wid;                 // candidate id, < 10048
        float4 acc = make_float4(0.f, 0.f, 0.f, 0.f);
        if (c < NCN) {
            int is64 = detect64(cand);
            int idx[NCL];
            if (is64) {
                const int* p = cand + (size_t)c * NCL * 2;
#pragma unroll
                for (int l = 0; l < NCL; l++) idx[l] = p[2 * l];
            } else {
                const int* p = cand + (size_t)c * NCL;
#pragma unroll
                for (int l = 0; l < NCL; l++) idx[l] = p[l];
            }
#pragma unroll
            for (int l0 = 0; l0 < NCL; l0 += 5) {
                float4 v[5];
#pragma unroll
                for (int j = 0; j < 5; j++)
                    v[j] = W4[(size_t)idx[l0 + j] * 32 + lane];
#pragma unroll
                for (int j = 0; j < 5; j++)
                    if (idx[l0 + j] != 0) {
                        acc.x += v[j].x; acc.y += v[j].y;
                        acc.z += v[j].z; acc.w += v[j].w;
                    }
            }
        }
        *reinterpret_cast<float4*>(&s_cs[wid][lane * 4]) = acc;
        __syncthreads();
        // transpose out: thread t -> (k = t>>1, ch = (t&1)*4), 32B/row chunks
        int k  = tid >> 1;
        int ch = (tid & 1) * 4;
        float4 o = make_float4(s_cs[ch + 0][k], s_cs[ch + 1][k],
                               s_cs[ch + 2][k], s_cs[ch + 3][k]);
        reinterpret_cast<float4*>(g_csT)[(size_t)k * (NCP / 4) + cb * 2 + (ch >> 2)] = o;
    }
}

// ---------------------------------------------------------------------------
// K2: one block (512 threads) per b. Streams m[b] + H into smem, 3 hops.
__global__ __launch_bounds__(512) void k_hops(const int* __restrict__ queries,
                                              const float* __restrict__ A,
                                              const float* __restrict__ Hw) {
    extern __shared__ float sm[];
    float* sm_m    = sm;                       // NM*ND = 25600 floats
    float* sm_H    = sm_m + NM * ND;           // 16384
    float* sm_u    = sm_H + ND * ND;           // 128
    float* sm_dot  = sm_u + ND;                // 200
    float* sm_prob = sm_dot + NM;              // 200
    float* sm_o    = sm_prob + NM;             // 256  [2][128] partials
    float* sm_hu   = sm_o + 2 * ND;            // 256  [2][128] partials
    float* sm_red  = sm_hu + 2 * ND;           // 64

    int b    = blockIdx.x;
    int tid  = threadIdx.x;
    int lane = tid & 31;
    int wid  = tid >> 5;     // 0..15

    const float4* gm4 = reinterpret_cast<const float4*>(g_m) + (size_t)b * NM * 32;
    float4* smm4 = reinterpret_cast<float4*>(sm_m);
    for (int i = tid; i < NM * 32; i += 512) smm4[i] = gm4[i];
    const float4* H4 = reinterpret_cast<const float4*>(Hw);
    float4* smH4 = reinterpret_cast<float4*>(sm_H);
    for (int i = tid; i < 4096; i += 512) smH4[i] = H4[i];

    if (tid < ND) {
        int is64 = detect64(queries);
        int idx[NS];
        if (is64) {
            const int* p = queries + (size_t)b * NS * 2;
#pragma unroll
            for (int s = 0; s < NS; s++) idx[s] = p[2 * s];
        } else {
            const int* p = queries + (size_t)b * NS;
#pragma unroll
            for (int s = 0; s < NS; s++) idx[s] = p[s];
        }
        float u = 0.f;
#pragma unroll
        for (int c0 = 0; c0 < NS; c0 += 5) {
            float v[5];
#pragma unroll
            for (int j = 0; j < 5; j++) v[j] = A[(size_t)idx[c0 + j] * ND + tid];
#pragma unroll
            for (int j = 0; j < 5; j++) if (idx[c0 + j] != 0) u += v[j];
        }
        sm_u[tid] = u;
    }
    __syncthreads();

    for (int hop = 0; hop < 3; hop++) {
        // dotted[mm] = dot(m[mm], u)
        float4 u4 = reinterpret_cast<float4*>(sm_u)[lane];
#pragma unroll
        for (int t = 0; t < 13; t++) {
            int mm = wid + 16 * t;
            if (mm < NM) {
                float4 mv = reinterpret_cast<float4*>(sm_m)[mm * 32 + lane];
                float d = mv.x * u4.x + mv.y * u4.y + mv.z * u4.z + mv.w * u4.w;
#pragma unroll
                for (int o = 16; o; o >>= 1) d += __shfl_xor_sync(0xffffffffu, d, o);
                if (lane == 0) sm_dot[mm] = d;
            }
        }
        __syncthreads();

        // softmax over 200 (16-warp block reduce)
        float v = (tid < NM) ? sm_dot[tid] : -1e30f;
        float r = v;
#pragma unroll
        for (int o = 16; o; o >>= 1) r = fmaxf(r, __shfl_xor_sync(0xffffffffu, r, o));
        if (lane == 0) sm_red[wid] = r;
        __syncthreads();
        if (tid < 32) {
            float rr = (tid < 16) ? sm_red[tid] : -1e30f;
#pragma unroll
            for (int o = 8; o; o >>= 1) rr = fmaxf(rr, __shfl_xor_sync(0xffffffffu, rr, o));
            if (tid == 0) sm_red[32] = rr;
        }
        __syncthreads();
        float mx = sm_red[32];
        float e = (tid < NM) ? __expf(v - mx) : 0.f;
        if (tid < NM) sm_prob[tid] = e;
        float s = e;
#pragma unroll
        for (int o = 16; o; o >>= 1) s += __shfl_xor_sync(0xffffffffu, s, o);
        if (lane == 0) sm_red[wid] = s;
        __syncthreads();
        if (tid < 32) {
            float ss = (tid < 16) ? sm_red[tid] : 0.f;
#pragma unroll
            for (int o = 8; o; o >>= 1) ss += __shfl_xor_sync(0xffffffffu, ss, o);
            if (tid == 0) sm_red[33] = ss;
        }
        __syncthreads();
        float inv = 1.0f / sm_red[33];

        // [0,256): o-partials over mm-halves; [256,512): Hu-partials, diag swizzle
        if (tid < 2 * ND) {
            int d = tid & (ND - 1), h = tid >> 7;
            float o = 0.f;
            int m0 = h * 100;
#pragma unroll 4
            for (int mm = m0; mm < m0 + 100; mm++) o += sm_prob[mm] * sm_m[mm * ND + d];
            sm_o[h * ND + d] = o;
        } else {
            int t2 = tid - 2 * ND;
            int d = t2 & (ND - 1), h = t2 >> 7;
            float hu = 0.f;
            int j0 = h * 64;
#pragma unroll 4
            for (int j = j0; j < j0 + 64; j++) {
                int dp = (d + j) & (ND - 1);
                hu += sm_H[d * ND + dp] * sm_u[dp];
            }
            sm_hu[h * ND + d] = hu;
        }
        __syncthreads();
        if (tid < ND)
            sm_u[tid] = tanhf(sm_hu[tid] + sm_hu[ND + tid]
                              + (sm_o[tid] + sm_o[ND + tid]) * inv);
        __syncthreads();
    }
    // transposed write: g_uT[d][b]
    if (tid < ND) g_uT[tid * NB + b] = sm_u[tid];
}

// ---------------------------------------------------------------------------
// K3: GEMM out[128,10000] = U @ CS^T. grid 148 (1 CTA/SM), block 128 (16tx x 8ty).
// Pass1: 8b x 8c tile over 64 cands; pass2: 4-cand remainder (blocks < 132).
#define FFMA2(acc, a, b) \
    asm("fma.rn.f32x2 %0, %1, %2, %0;" : "+l"(acc) : "l"(a), "l"(b))

__device__ __forceinline__ unsigned long long dup2(float x) {
    unsigned long long r;
    asm("mov.b64 %0, {%1, %1};" : "=l"(r) : "f"(x));
    return r;
}

__global__ __launch_bounds__(128) void k_logits(float* __restrict__ out) {
    extern __shared__ float sm[];
    float* uT  = sm;                 // [128][132]  (row = 33 float4)
    float* csT = sm + ND * 132;      // [128][72]   (row = 18 float4); reused as sm_out[128][72]
    int tid = threadIdx.x;
    int tx  = tid & 15;              // b-group
    int ty  = tid >> 4;              // c-group 0..7
    int bid = blockIdx.x;
    int cmain  = bid * 64;                       // [0,9472)
    int rstart = 9472 + bid * 4;
    int rcnt   = (bid < 132) ? 4 : 0;

    // stage uT (4096 float4) with pad-33 rows
    {
        const float4* gu4 = reinterpret_cast<const float4*>(g_uT);
        float4* u4 = reinterpret_cast<float4*>(uT);
        for (int i = tid; i < 4096; i += 128)
            u4[(i >> 5) * 33 + (i & 31)] = gu4[i];
    }
    // stage csT main 64 cols (2048 float4) + rem 4 cols (128 float4)
    {
        const float4* gc4 = reinterpret_cast<const float4*>(g_csT);
        float4* c4 = reinterpret_cast<float4*>(csT);
        for (int i = tid; i < 2048; i += 128) {
            int k = i >> 4, j = i & 15;
            c4[k * 18 + j] = gc4[(size_t)k * (NCP / 4) + bid * 16 + j];
        }
        if (tid < 128) {
            int k = tid;
            float4 v = rcnt ? gc4[(size_t)k * (NCP / 4) + 2368 + bid]
                            : make_float4(0.f, 0.f, 0.f, 0.f);
            c4[k * 18 + 16] = v;
        }
    }
    __syncthreads();

    // ---- pass1: 8b x 8c, c-pair FFMA2 accumulators ----
    unsigned long long acc[8][4];
#pragma unroll
    for (int i = 0; i < 8; i++)
#pragma unroll
        for (int j = 0; j < 4; j++) acc[i][j] = 0ull;

    const float4* u4 = reinterpret_cast<const float4*>(uT);
#pragma unroll 4
    for (int k = 0; k < ND; k++) {
        float4 ua = u4[k * 33 + tx];           // b = tx*4 .. +3
        float4 ub = u4[k * 33 + 16 + tx];      // b = 64+tx*4 .. +3
        ulonglong2 ca = *reinterpret_cast<const ulonglong2*>(csT + k * 72 + ty * 8);
        ulonglong2 cb = *reinterpret_cast<const ulonglong2*>(csT + k * 72 + ty * 8 + 4);
        unsigned long long du[8];
        du[0] = dup2(ua.x); du[1] = dup2(ua.y); du[2] = dup2(ua.z); du[3] = dup2(ua.w);
        du[4] = dup2(ub.x); du[5] = dup2(ub.y); du[6] = dup2(ub.z); du[7] = dup2(ub.w);
#pragma unroll
        for (int i = 0; i < 8; i++) {
            FFMA2(acc[i][0], du[i], ca.x);
            FFMA2(acc[i][1], du[i], ca.y);
            FFMA2(acc[i][2], du[i], cb.x);
            FFMA2(acc[i][3], du[i], cb.y);
        }
    }

    // ---- pass2: remainder 4 candidates, thread = (c = tid&3, b-group = tid>>2) ----
    float racc[4] = {0.f, 0.f, 0.f, 0.f};
    if (rcnt) {
        int rc = tid & 3;
        int g  = tid >> 2;             // 0..31
        for (int k = 0; k < ND; k++) {
            float cv = csT[k * 72 + 64 + rc];
#pragma unroll
            for (int i = 0; i < 4; i++)
                racc[i] += uT[k * 132 + g + 32 * i] * cv;
        }
    }
    __syncthreads();   // done reading csT/uT; reuse csT region as sm_out

    // ---- epilogue: acc -> sm_out[b][72], then coalesced global stores ----
    float* sm_out = csT;
#pragma unroll
    for (int i = 0; i < 8; i++) {
        int b = (i < 4) ? (tx * 4 + i) : (64 + tx * 4 + (i - 4));
#pragma unroll
        for (int j = 0; j < 4; j++)
            *reinterpret_cast<unsigned long long*>(sm_out + b * 72 + ty * 8 + 2 * j) = acc[i][j];
    }
    if (rcnt) {
        int rc = tid & 3, g = tid >> 2;
#pragma unroll
        for (int i = 0; i < 4; i++)
            sm_out[(g + 32 * i) * 72 + 64 + rc] = racc[i];
    }
    __syncthreads();

    for (int i = tid; i < NB * 64; i += 128) {
        int b = i >> 6, c = i & 63;
        out[(size_t)b * NCN + cmain + c] = sm_out[b * 72 + c];
    }
    if (rcnt) {
        for (int i = tid; i < NB * 4; i += 128) {
            int b = i >> 2, c = i & 3;
            out[(size_t)b * NCN + rstart + c] = sm_out[b * 72 + 64 + c];
        }
    }
}

// ---------------------------------------------------------------------------
extern "C" void kernel_launch(void* const* d_in, const int* in_sizes, int n_in,
                              void* d_out, int out_size) {
    const int*    stories = (const int*)d_in[0];
    const int*    queries = (const int*)d_in[1];
    const int*    cand    = (const int*)d_in[2];
    const float*  A_tab   = (const float*)d_in[3];
    const float*  W_tab   = (const float*)d_in[4];
    const float*  H_w     = (const float*)d_in[5];
    float* out = (float*)d_out;

    const int hops_smem   = (NM * ND + ND * ND + ND + NM + NM + 2 * ND + 2 * ND + 64) * 4; // 172352 B
    const int logits_smem = (ND * 132 + ND * 72) * 4;                                      // 104448 B
    cudaFuncSetAttribute(k_hops,   cudaFuncAttributeMaxDynamicSharedMemorySize, hops_smem);
    cudaFuncSetAttribute(k_logits, cudaFuncAttributeMaxDynamicSharedMemorySize, logits_smem);

    k_gather<<<3200 + NCP / 8, 256>>>(stories, cand, (const float4*)A_tab,
                                      (const float4*)W_tab);
    k_hops<<<NB, 512, hops_smem>>>(queries, A_tab, H_w);
    k_logits<<<148, 128, logits_smem>>>(out);
}

// round 10
// speedup vs baseline: 1.0428x; 1.0428x over previous
#include <cuda_runtime.h>

// MemN2N on GB300 (sm_103a)
// B=128, M=200, S=20, D=128, V=100000, NC=10000, CL=10, 3 hops.
// Inputs: stories(i64), queries(i64), candidates(i64),
//         A_tab(f32 V*D), W_tab(f32 V*D), H_w(f32 D*D)
// Output: logits f32 [B, NC]
//
// K1 k_gather: story gathers only -> g_m. 262 MB L2->SM, LTS-cap bound (~22.8us).
// K2 k_hops:   768 threads: warps 0-15 hop path (named bar 1), warps 16-23
//              candidate gather -> g_csT transposed (named bar 2), overlapped.
// K3 k_logits: GEMM out = U @ CS^T; 256 thr, grid 148, 8b x 4c tile,
//              natural b-pair FFMA2 accumulators from ulonglong2 uT loads.

#define NB   128
#define NM   200
#define NS   20
#define ND   128
#define NCN  10000
#define NCP  10048   // padded candidate count (1256 * 8)
#define NCL  10

__device__ float g_m[NB * NM * ND];     // 13.1 MB memory encodings
__device__ float g_csT[ND * NCP];       // 5.1 MB candidate sums, TRANSPOSED [k][c]
__device__ float g_uT[ND * NB];         // query state after hops, TRANSPOSED [k][b]

#define HBAR() asm volatile("bar.sync 1, 512;" ::: "memory")
#define GBAR() asm volatile("bar.sync 2, 256;" ::: "memory")

__device__ __forceinline__ int detect64(const int* __restrict__ p) {
    // values < 100000: if int64 (LE), high words of first elements are 0.
    return (p[1] == 0 && p[3] == 0 && p[5] == 0 && p[7] == 0) ? 1 : 0;
}

// ---------------------------------------------------------------------------
// K1: story gathers. Warp w -> m[w][:] = sum_s A[stories[w][s]].
__global__ __launch_bounds__(256) void k_gather(const int* __restrict__ stories,
                                                const float4* __restrict__ A4) {
    int w    = blockIdx.x * 8 + (threadIdx.x >> 5);
    int lane = threadIdx.x & 31;
    int is64 = detect64(stories);
    int idx[NS];
    if (is64) {
        const int* p = stories + (size_t)w * NS * 2;
#pragma unroll
        for (int s = 0; s < NS; s++) idx[s] = p[2 * s];
    } else {
        const int* p = stories + (size_t)w * NS;
#pragma unroll
        for (int s = 0; s < NS; s++) idx[s] = p[s];
    }
    float4 acc = make_float4(0.f, 0.f, 0.f, 0.f);
#pragma unroll
    for (int c0 = 0; c0 < NS; c0 += 5) {
        float4 v[5];
#pragma unroll
        for (int j = 0; j < 5; j++)
            v[j] = A4[(size_t)idx[c0 + j] * 32 + lane];   // row 0 valid
#pragma unroll
        for (int j = 0; j < 5; j++)
            if (idx[c0 + j] != 0) {
                acc.x += v[j].x; acc.y += v[j].y;
                acc.z += v[j].z; acc.w += v[j].w;
            }
    }
    reinterpret_cast<float4*>(g_m)[(size_t)w * 32 + lane] = acc;
}

// ---------------------------------------------------------------------------
// K2: 768 threads per block, one block per b.
//   tid <  512: hop path (stage m[b]+H, u0, 3 hops) — all syncs are bar 1.
//   tid >= 512: 8 warps gather 80 candidates into g_csT — syncs are bar 2.
__global__ __launch_bounds__(768) void k_hops(const int* __restrict__ queries,
                                              const int* __restrict__ cand,
                                              const float* __restrict__ A,
                                              const float4* __restrict__ W4,
                                              const float* __restrict__ Hw) {
    extern __shared__ float sm[];
    float* sm_m    = sm;                       // 25600
    float* sm_H    = sm_m + NM * ND;           // 16384
    float* sm_u    = sm_H + ND * ND;           // 128
    float* sm_dot  = sm_u + ND;                // 200
    float* sm_prob = sm_dot + NM;              // 200
    float* sm_o    = sm_prob + NM;             // 256 [2][128]
    float* sm_hu   = sm_o + 2 * ND;            // 256 [2][128]
    float* sm_red  = sm_hu + 2 * ND;           // 64
    float* s_cs    = sm_red + 64;              // 8*128 gather transpose buffer

    int b    = blockIdx.x;
    int tid  = threadIdx.x;
    int lane = tid & 31;
    int wid  = tid >> 5;

    if (tid >= 512) {
        // ---------------- candidate-gather warps ----------------
        int gt    = tid - 512;        // 0..255
        int gw    = gt >> 5;          // 0..7
        int is64  = detect64(cand);
        for (int it = 0; it < 10; it++) {
            int cb = b * 10 + it;     // transpose batch id (8 cands)
            int c  = cb * 8 + gw;
            float4 acc = make_float4(0.f, 0.f, 0.f, 0.f);
            if (c < NCN) {
                int idx[NCL];
                if (is64) {
                    const int* p = cand + (size_t)c * NCL * 2;
#pragma unroll
                    for (int l = 0; l < NCL; l++) idx[l] = p[2 * l];
                } else {
                    const int* p = cand + (size_t)c * NCL;
#pragma unroll
                    for (int l = 0; l < NCL; l++) idx[l] = p[l];
                }
#pragma unroll
                for (int l0 = 0; l0 < NCL; l0 += 5) {
                    float4 v[5];
#pragma unroll
                    for (int j = 0; j < 5; j++)
                        v[j] = W4[(size_t)idx[l0 + j] * 32 + lane];
#pragma unroll
                    for (int j = 0; j < 5; j++)
                        if (idx[l0 + j] != 0) {
                            acc.x += v[j].x; acc.y += v[j].y;
                            acc.z += v[j].z; acc.w += v[j].w;
                        }
                }
            }
            if (cb < NCP / 8) {       // uniform within gather group
                *reinterpret_cast<float4*>(&s_cs[gw * 128 + lane * 4]) = acc;
                GBAR();
                int k  = gt >> 1;
                int ch = (gt & 1) * 4;
                float4 o = make_float4(s_cs[(ch + 0) * 128 + k], s_cs[(ch + 1) * 128 + k],
                                       s_cs[(ch + 2) * 128 + k], s_cs[(ch + 3) * 128 + k]);
                reinterpret_cast<float4*>(g_csT)[(size_t)k * (NCP / 4) + cb * 2 + (ch >> 2)] = o;
                GBAR();
            }
        }
        return;
    }

    // ---------------- hop warps (512 threads) ----------------
    const float4* gm4 = reinterpret_cast<const float4*>(g_m) + (size_t)b * NM * 32;
    float4* smm4 = reinterpret_cast<float4*>(sm_m);
    for (int i = tid; i < NM * 32; i += 512) smm4[i] = gm4[i];
    const float4* H4 = reinterpret_cast<const float4*>(Hw);
    float4* smH4 = reinterpret_cast<float4*>(sm_H);
    for (int i = tid; i < 4096; i += 512) smH4[i] = H4[i];

    if (tid < ND) {
        int is64 = detect64(queries);
        int idx[NS];
        if (is64) {
            const int* p = queries + (size_t)b * NS * 2;
#pragma unroll
            for (int s = 0; s < NS; s++) idx[s] = p[2 * s];
        } else {
            const int* p = queries + (size_t)b * NS;
#pragma unroll
            for (int s = 0; s < NS; s++) idx[s] = p[s];
        }
        float u = 0.f;
#pragma unroll
        for (int c0 = 0; c0 < NS; c0 += 5) {
            float v[5];
#pragma unroll
            for (int j = 0; j < 5; j++) v[j] = A[(size_t)idx[c0 + j] * ND + tid];
#pragma unroll
            for (int j = 0; j < 5; j++) if (idx[c0 + j] != 0) u += v[j];
        }
        sm_u[tid] = u;
    }
    HBAR();

    for (int hop = 0; hop < 3; hop++) {
        // dotted[mm] = dot(m[mm], u)
        float4 u4 = reinterpret_cast<float4*>(sm_u)[lane];
#pragma unroll
        for (int t = 0; t < 13; t++) {
            int mm = wid + 16 * t;
            if (mm < NM) {
                float4 mv = reinterpret_cast<float4*>(sm_m)[mm * 32 + lane];
                float d = mv.x * u4.x + mv.y * u4.y + mv.z * u4.z + mv.w * u4.w;
#pragma unroll
                for (int o = 16; o; o >>= 1) d += __shfl_xor_sync(0xffffffffu, d, o);
                if (lane == 0) sm_dot[mm] = d;
            }
        }
        HBAR();

        // softmax over 200
        float v = (tid < NM) ? sm_dot[tid] : -1e30f;
        float r = v;
#pragma unroll
        for (int o = 16; o; o >>= 1) r = fmaxf(r, __shfl_xor_sync(0xffffffffu, r, o));
        if (lane == 0) sm_red[wid] = r;
        HBAR();
        if (tid < 32) {
            float rr = (tid < 16) ? sm_red[tid] : -1e30f;
#pragma unroll
            for (int o = 8; o; o >>= 1) rr = fmaxf(rr, __shfl_xor_sync(0xffffffffu, rr, o));
            if (tid == 0) sm_red[32] = rr;
        }
        HBAR();
        float mx = sm_red[32];
        float e = (tid < NM) ? __expf(v - mx) : 0.f;
        if (tid < NM) sm_prob[tid] = e;
        float s = e;
#pragma unroll
        for (int o = 16; o; o >>= 1) s += __shfl_xor_sync(0xffffffffu, s, o);
        if (lane == 0) sm_red[wid] = s;
        HBAR();
        if (tid < 32) {
            float ss = (tid < 16) ? sm_red[tid] : 0.f;
#pragma unroll
            for (int o = 8; o; o >>= 1) ss += __shfl_xor_sync(0xffffffffu, ss, o);
            if (tid == 0) sm_red[33] = ss;
        }
        HBAR();
        float inv = 1.0f / sm_red[33];

        if (tid < 2 * ND) {
            int d = tid & (ND - 1), h = tid >> 7;
            float o = 0.f;
            int m0 = h * 100;
#pragma unroll 4
            for (int mm = m0; mm < m0 + 100; mm++) o += sm_prob[mm] * sm_m[mm * ND + d];
            sm_o[h * ND + d] = o;
        } else {
            int t2 = tid - 2 * ND;
            int d = t2 & (ND - 1), h = t2 >> 7;
            float hu = 0.f;
            int j0 = h * 64;
#pragma unroll 4
            for (int j = j0; j < j0 + 64; j++) {
                int dp = (d + j) & (ND - 1);
                hu += sm_H[d * ND + dp] * sm_u[dp];
            }
            sm_hu[h * ND + d] = hu;
        }
        HBAR();
        if (tid < ND)
            sm_u[tid] = tanhf(sm_hu[tid] + sm_hu[ND + tid]
                              + (sm_o[tid] + sm_o[ND + tid]) * inv);
        HBAR();
    }
    if (tid < ND) g_uT[tid * NB + b] = sm_u[tid];   // transposed write
}

// ---------------------------------------------------------------------------
// K3: GEMM out[128,10000] = U @ CS^T. grid 148, block 256 (tx 16 x ty 16).
// Thread tile 8b x 4c: per k, 2 ulonglong2 u loads (natural b-pairs, zero
// packing) + 1 float4 cs load + 4 dup movs + 16 FFMA2.
#define FFMA2(acc, a, b) \
    asm("fma.rn.f32x2 %0, %1, %2, %0;" : "+l"(acc) : "l"(a), "l"(b))

__device__ __forceinline__ unsigned long long dup2(float x) {
    unsigned long long r;
    asm("mov.b64 %0, {%1, %1};" : "=l"(r) : "f"(x));
    return r;
}
__device__ __forceinline__ void unpack2(unsigned long long v, float& lo, float& hi) {
    asm("mov.b64 {%0,%1}, %2;" : "=f"(lo), "=f"(hi) : "l"(v));
}

__global__ __launch_bounds__(256) void k_logits(float* __restrict__ out) {
    extern __shared__ float sm[];
    float* uT  = sm;                 // [128][132] (row = 33 float4)
    float* csT = sm + ND * 132;      // [128][76]; cols 0..63 main, 64..67 rem; reused as sm_out
    int tid = threadIdx.x;
    int tx  = tid & 15;              // b-group: b = tx*4 and 64+tx*4
    int ty  = tid >> 4;              // c-group 0..15: c = ty*4
    int bid = blockIdx.x;
    int cmain  = bid * 64;                       // [0,9472)
    int rcnt   = (bid < 132) ? 4 : 0;

    // stage uT (4096 float4), pad-33 rows
    {
        const float4* gu4 = reinterpret_cast<const float4*>(g_uT);
        float4* u4 = reinterpret_cast<float4*>(uT);
        for (int i = tid; i < 4096; i += 256)
            u4[(i >> 5) * 33 + (i & 31)] = gu4[i];
    }
    // stage csT: main 64 cols (16 float4/row) + rem 4 cols
    {
        const float4* gc4 = reinterpret_cast<const float4*>(g_csT);
        float4* c4 = reinterpret_cast<float4*>(csT);
        for (int i = tid; i < 2048; i += 256) {
            int k = i >> 4, j = i & 15;
            c4[k * 19 + j] = gc4[(size_t)k * (NCP / 4) + bid * 16 + j];
        }
        if (tid < 128) {
            int k = tid;
            float4 v = rcnt ? gc4[(size_t)k * (NCP / 4) + 2368 + bid]
                            : make_float4(0.f, 0.f, 0.f, 0.f);
            c4[k * 19 + 16] = v;
        }
    }
    __syncthreads();

    // ---- main: 8b x 4c, b-pair FFMA2 accumulators ----
    unsigned long long acc[4][4];
#pragma unroll
    for (int i = 0; i < 4; i++)
#pragma unroll
        for (int j = 0; j < 4; j++) acc[i][j] = 0ull;

#pragma unroll 4
    for (int k = 0; k < ND; k++) {
        ulonglong2 ua = *reinterpret_cast<const ulonglong2*>(uT + k * 132 + tx * 4);
        ulonglong2 ub = *reinterpret_cast<const ulonglong2*>(uT + k * 132 + 64 + tx * 4);
        float4 cv = *reinterpret_cast<const float4*>(csT + k * 76 + ty * 4);
        unsigned long long dc[4];
        dc[0] = dup2(cv.x); dc[1] = dup2(cv.y); dc[2] = dup2(cv.z); dc[3] = dup2(cv.w);
#pragma unroll
        for (int j = 0; j < 4; j++) {
            FFMA2(acc[0][j], ua.x, dc[j]);
            FFMA2(acc[1][j], ua.y, dc[j]);
            FFMA2(acc[2][j], ub.x, dc[j]);
            FFMA2(acc[3][j], ub.y, dc[j]);
        }
    }

    // ---- remainder: 4 candidates (cols 64..67), thread = (rc, g) ----
    float racc[2] = {0.f, 0.f};
    if (rcnt) {
        int rc = tid & 3;
        int g  = tid >> 2;             // 0..63
        for (int k = 0; k < ND; k++) {
            float cv = csT[k * 76 + 64 + rc];
            racc[0] += uT[k * 132 + g] * cv;
            racc[1] += uT[k * 132 + 64 + g] * cv;
        }
    }
    __syncthreads();   // done reading; reuse csT as sm_out[128][76]

    float* sm_out = csT;
#pragma unroll
    for (int i = 0; i < 4; i++) {
        int b = (i < 2) ? (tx * 4 + 2 * i) : (64 + tx * 4 + 2 * (i - 2));
#pragma unroll
        for (int j = 0; j < 4; j++) {
            float lo, hi;
            unpack2(acc[i][j], lo, hi);
            sm_out[b * 76 + ty * 4 + j]       = lo;
            sm_out[(b + 1) * 76 + ty * 4 + j] = hi;
        }
    }
    if (rcnt) {
        int rc = tid & 3, g = tid >> 2;
        sm_out[g * 76 + 64 + rc]        = racc[0];
        sm_out[(64 + g) * 76 + 64 + rc] = racc[1];
    }
    __syncthreads();

    for (int i = tid; i < NB * 64; i += 256) {
        int b = i >> 6, c = i & 63;
        out[(size_t)b * NCN + cmain + c] = sm_out[b * 76 + c];
    }
    if (rcnt) {
        int rstart = 9472 + bid * 4;
        for (int i = tid; i < NB * 4; i += 256) {
            int b = i >> 2, c = i & 3;
            out[(size_t)b * NCN + rstart + c] = sm_out[b * 76 + 64 + c];
        }
    }
}

// ---------------------------------------------------------------------------
extern "C" void kernel_launch(void* const* d_in, const int* in_sizes, int n_in,
                              void* d_out, int out_size) {
    const int*    stories = (const int*)d_in[0];
    const int*    queries = (const int*)d_in[1];
    const int*    cand    = (const int*)d_in[2];
    const float*  A_tab   = (const float*)d_in[3];
    const float*  W_tab   = (const float*)d_in[4];
    const float*  H_w     = (const float*)d_in[5];
    float* out = (float*)d_out;

    const int hops_smem   = (NM * ND + ND * ND + ND + NM + NM + 2 * ND + 2 * ND + 64
                             + 8 * 128) * 4;                    // 176448 B
    const int logits_smem = (ND * 132 + ND * 76) * 4;           // 106496 B
    cudaFuncSetAttribute(k_hops,   cudaFuncAttributeMaxDynamicSharedMemorySize, hops_smem);
    cudaFuncSetAttribute(k_logits, cudaFuncAttributeMaxDynamicSharedMemorySize, logits_smem);

    k_gather<<<(NB * NM) / 8, 256>>>(stories, (const float4*)A_tab);
    k_hops<<<NB, 768, hops_smem>>>(queries, cand, A_tab, (const float4*)W_tab, H_w);
    k_logits<<<148, 256, logits_smem>>>(out);
}